// round 11
// baseline (speedup 1.0000x reference)
#include <cuda_runtime.h>
#include <math.h>

// Problem constants
#define Bv   128
#define Tn   128
#define Cn   256
#define Hn   4
#define Ln   6
#define Vn   10000
#define HSn  64
#define DFFn 1024
#define BT   (Bv*Tn)   // 16384 rows

// ---------------- scratch (device globals; no allocation allowed) ----------
__device__ float g_X  [BT*Cn];      // residual stream
__device__ float g_Hb [BT*Cn];      // layernorm output (tf32-rounded)
__device__ float g_QKV[BT*768];     // fused QKV output [row][768]
__device__ float g_Att[BT*Cn];      // attention out (tf32-rounded)
__device__ float g_FF [BT*DFFn];    // relu MLP hidden (tf32-rounded)

// pre-rounded weights, [n][k] layout with k-pair permutation
#define RW_QKV 0                        // [L][768][256]
#define RW_PJ  1179648                  // [L][256][256]
#define RW_W1  1572864                  // [L][1024][256]
#define RW_W2  3145728                  // [L][256][1024]
#define RW_LM  4718592                  // [10000][256]
#define RW_TOT 7278592
__device__ float g_rW [RW_TOT];

// ---------------- helpers ---------------------------------------------------
__device__ __forceinline__ unsigned f2tf32(float x) {
    unsigned r;
    asm("cvt.rna.tf32.f32 %0, %1;" : "=r"(r) : "f"(x));
    return r;
}
__device__ __forceinline__ float roundtf(float x) {
    return __uint_as_float(f2tf32(x));
}

__device__ __forceinline__ void mma_tf32(float* c, const unsigned* a, const unsigned* b) {
    asm volatile(
        "mma.sync.aligned.m16n8k8.row.col.f32.tf32.tf32.f32 "
        "{%0,%1,%2,%3}, {%4,%5,%6,%7}, {%8,%9}, {%0,%1,%2,%3};"
        : "+f"(c[0]), "+f"(c[1]), "+f"(c[2]), "+f"(c[3])
        : "r"(a[0]), "r"(a[1]), "r"(a[2]), "r"(a[3]), "r"(b[0]), "r"(b[1]));
}

__device__ __forceinline__ void cp16(unsigned dst_smem, const void* src) {
    asm volatile("cp.async.cg.shared.global [%0], [%1], 16;"
                 :: "r"(dst_smem), "l"(src));
}
__device__ __forceinline__ void cp16z(unsigned dst_smem, const void* src, int sz) {
    asm volatile("cp.async.cg.shared.global [%0], [%1], 16, %2;"
                 :: "r"(dst_smem), "l"(src), "r"(sz));
}
__device__ __forceinline__ void cp_commit() {
    asm volatile("cp.async.commit_group;" ::);
}
__device__ __forceinline__ void cp_wait1() {
    asm volatile("cp.async.wait_group 1;" ::);
}

// k-permutation inside each 16-k tile: pairs (k, k+4) adjacent.
// j = k&15 -> slot = (j>>3)*8 + (j&3)*2 + ((j>>2)&1)
__host__ __device__ __forceinline__ int kperm16(int k) {
    int j = k & 15;
    return (k & ~15) + ((j >> 3) << 3) + ((j & 3) << 1) + ((j >> 2) & 1);
}

// ---------------- weight pack: [K][N] -> [N][K] (k-pair permuted, tf32) -----
// grid: (ceil(N/32), K/32, L). in batch stride K*N, out batch stride outStride
__global__ void packBT_k(const float* __restrict__ in, float* __restrict__ out,
                         int K, int N, size_t outStride)
{
    __shared__ float t[32][33];
    const float* src = in + (size_t)blockIdx.z * K * N;
    float* dst = out + (size_t)blockIdx.z * outStride;
    int n0 = blockIdx.x * 32, k0 = blockIdx.y * 32;
    int tx = threadIdx.x & 31, ty = threadIdx.x >> 5;   // 256 thr: ty 0..7
    #pragma unroll
    for (int i = 0; i < 32; i += 8) {
        int k = k0 + ty + i, n = n0 + tx;
        t[ty + i][tx] = (n < N) ? src[(size_t)k * N + n] : 0.f;
    }
    __syncthreads();
    #pragma unroll
    for (int i = 0; i < 32; i += 8) {
        int n = n0 + ty + i, k = k0 + tx;
        if (n < N)
            dst[(size_t)n * K + kperm16(k)] = roundtf(t[tx][ty + i]);
    }
}

// ---------------- embedding ------------------------------------------------
__global__ void embed_k(const int* __restrict__ idx,
                        const float* __restrict__ tok,
                        const float* __restrict__ pos,
                        float* __restrict__ X)
{
    int bt = blockIdx.x;
    int c  = threadIdx.x;
    int t  = bt % Tn;
    int id = idx[bt];
    X[bt*Cn + c] = tok[id*Cn + c] + pos[t*Cn + c];
}

// ---------------- layernorm: one warp per row (shfl only) -------------------
__global__ void ln_k(const float* __restrict__ in, float* __restrict__ out,
                     const float* __restrict__ g, const float* __restrict__ b)
{
    int row  = blockIdx.x * 8 + (threadIdx.x >> 5);
    int lane = threadIdx.x & 31;
    const float* p = in + (size_t)row*Cn;

    float4 a = *(const float4*)(p + lane*4);
    float4 c = *(const float4*)(p + 128 + lane*4);
    float s = a.x+a.y+a.z+a.w + c.x+c.y+c.z+c.w;
    #pragma unroll
    for (int o = 16; o > 0; o >>= 1) s += __shfl_xor_sync(0xFFFFFFFF, s, o);
    float mean = s * (1.0f/Cn);

    float dx0=a.x-mean, dx1=a.y-mean, dx2=a.z-mean, dx3=a.w-mean;
    float dy0=c.x-mean, dy1=c.y-mean, dy2=c.z-mean, dy3=c.w-mean;
    float v = dx0*dx0+dx1*dx1+dx2*dx2+dx3*dx3 + dy0*dy0+dy1*dy1+dy2*dy2+dy3*dy3;
    #pragma unroll
    for (int o = 16; o > 0; o >>= 1) v += __shfl_xor_sync(0xFFFFFFFF, v, o);
    float r = rsqrtf(v * (1.0f/Cn) + 1e-5f);

    float4 ga = *(const float4*)(g + lane*4);
    float4 gc = *(const float4*)(g + 128 + lane*4);
    float4 ba = *(const float4*)(b + lane*4);
    float4 bc = *(const float4*)(b + 128 + lane*4);
    float* q = out + (size_t)row*Cn;
    float4 o1 = make_float4(roundtf(dx0*r*ga.x + ba.x), roundtf(dx1*r*ga.y + ba.y),
                            roundtf(dx2*r*ga.z + ba.z), roundtf(dx3*r*ga.w + ba.w));
    float4 o2 = make_float4(roundtf(dy0*r*gc.x + bc.x), roundtf(dy1*r*gc.y + bc.y),
                            roundtf(dy2*r*gc.z + bc.z), roundtf(dy3*r*gc.w + bc.w));
    *(float4*)(q + lane*4)       = o1;
    *(float4*)(q + 128 + lane*4) = o2;
}

// ---------------- TF32 GEMM: 3-stage ring + LDS.64 B fragments --------------
// C = A[M,K] * Bt[N,K]^T (Bt k-pair permuted). BM=BN=128, BK=16, 8 warps.
// A stage: 128x20 words; B stage: 128 n x 24 words (stride 24 -> LDS.64 CF).
// EPI bit0 = +bias[n], bit1 = +res, bit2 = relu, bit3 = round output to tf32
#define GM_AS_W   2560            // 128*20
#define GM_BS_W   3072            // 128*24
#define GM_STAGES 3
#define GM_SMEM_W (GM_STAGES*(GM_AS_W + GM_BS_W))
#define GM_SMEM_B (GM_SMEM_W*4)   // 67584 bytes

template<int EPI>
__global__ void __launch_bounds__(256, 2)
tcgemm_k(int M, int N, int K,
         const float* __restrict__ A, int lda,
         const float* __restrict__ Bt,   // [N][K] permuted, ldb == K
         const float* __restrict__ bias,
         const float* __restrict__ res,
         float* __restrict__ C, int ldc)
{
    extern __shared__ unsigned dynsm[];

    int tid  = threadIdx.x;
    int wid  = tid >> 5, lane = tid & 31;
    int grp  = lane >> 2, tg = lane & 3;
    int wm   = (wid & 3) * 32;
    int wn   = (wid >> 2) * 64;
    int bm   = blockIdx.y * 128, bn = blockIdx.x * 128;

    float acc[2][8][4];
    #pragma unroll
    for (int mt = 0; mt < 2; mt++)
        #pragma unroll
        for (int nt = 0; nt < 8; nt++)
            #pragma unroll
            for (int r = 0; r < 4; r++) acc[mt][nt][r] = 0.f;

    int niter = K >> 4;

    auto issue = [&](int slot, int k0) {
        unsigned* As = dynsm + slot*(GM_AS_W + GM_BS_W);
        unsigned* Bs = As + GM_AS_W;
        #pragma unroll
        for (int it = 0; it < 2; it++) {
            int c = tid + it*256;
            int row = c >> 2, kc = (c & 3) * 4;
            unsigned d = (unsigned)__cvta_generic_to_shared(As + row*20 + kc);
            cp16(d, A + (size_t)(bm + row)*lda + k0 + kc);
        }
        #pragma unroll
        for (int it = 0; it < 2; it++) {
            int c = tid + it*256;
            int n = c >> 2, c4 = c & 3;        // 4 threads cover one n's 64B
            unsigned d = (unsigned)__cvta_generic_to_shared(Bs + n*24 + c4*4);
            int col = bn + n;
            cp16z(d, Bt + (size_t)(col < N ? col : 0)*K + k0 + c4*4,
                  col < N ? 16 : 0);
        }
    };

    // prologue: stages 0,1
    issue(0, 0); cp_commit();
    if (niter > 1) { issue(1, 16); }
    cp_commit();

    for (int i = 0; i < niter; i++) {
        int slot = i % GM_STAGES;
        cp_wait1();            // stage i's group complete
        __syncthreads();       // slot (i+2)%3 == (i-1)%3 fully consumed

        if (i + 2 < niter) issue((i + 2) % GM_STAGES, (i + 2) << 4);
        cp_commit();

        unsigned* As = dynsm + slot*(GM_AS_W + GM_BS_W);
        unsigned* Bs = As + GM_AS_W;

        #pragma unroll
        for (int ks = 0; ks < 2; ks++) {
            int k = ks*8;
            uint2 bfr[8];
            #pragma unroll
            for (int nt = 0; nt < 8; nt++)
                bfr[nt] = *(uint2*)(Bs + (wn + nt*8 + grp)*24 + ks*8 + tg*2);
            #pragma unroll
            for (int mt = 0; mt < 2; mt++) {
                unsigned afr[4];
                afr[0] = As[(wm + mt*16 + grp    )*20 + k + tg    ];
                afr[1] = As[(wm + mt*16 + grp + 8)*20 + k + tg    ];
                afr[2] = As[(wm + mt*16 + grp    )*20 + k + tg + 4];
                afr[3] = As[(wm + mt*16 + grp + 8)*20 + k + tg + 4];
                #pragma unroll
                for (int nt = 0; nt < 8; nt++)
                    mma_tf32(acc[mt][nt], afr, (const unsigned*)&bfr[nt]);
            }
        }
    }

    // epilogue
    #pragma unroll
    for (int mt = 0; mt < 2; mt++) {
        int r0 = bm + wm + mt*16 + grp;
        #pragma unroll
        for (int nt = 0; nt < 8; nt++) {
            int c0 = bn + wn + nt*8 + 2*tg;
            #pragma unroll
            for (int half = 0; half < 2; half++) {
                int r = r0 + half*8;
                float v0 = acc[mt][nt][half*2+0];
                float v1 = acc[mt][nt][half*2+1];
                if (c0 < N) {
                    if (EPI & 1) v0 += bias[c0];
                    if (EPI & 2) v0 += res[(size_t)r*ldc + c0];
                    if (EPI & 4) v0 = fmaxf(v0, 0.f);
                    if (EPI & 8) v0 = roundtf(v0);
                    C[(size_t)r*ldc + c0] = v0;
                }
                if (c0 + 1 < N) {
                    if (EPI & 1) v1 += bias[c0+1];
                    if (EPI & 2) v1 += res[(size_t)r*ldc + c0+1];
                    if (EPI & 4) v1 = fmaxf(v1, 0.f);
                    if (EPI & 8) v1 = roundtf(v1);
                    C[(size_t)r*ldc + c0+1] = v1;
                }
            }
        }
    }
}

// ---------------- fused flash attention (tensor cores) ----------------------
#define ATT_QS   0
#define ATT_KS   9216
#define ATT_VS   17728
#define ATT_PS   26944
#define ATT_WORDS 43840
#define ATT_BYTES (ATT_WORDS*4)

__global__ void __launch_bounds__(256, 1)
attn_k(const float* __restrict__ QKV, float* __restrict__ Att)
{
    extern __shared__ unsigned sm[];
    unsigned* smQ = sm + ATT_QS;
    unsigned* smK = sm + ATT_KS;
    unsigned* smV = sm + ATT_VS;

    int bh = blockIdx.x;
    int b = bh >> 2, h = bh & 3;
    const float* Qp = QKV + (size_t)b*Tn*768 + h*HSn;

    int tid = threadIdx.x;
    int wid = tid >> 5, lane = tid & 31;
    int grp = lane >> 2, tg = lane & 3;
    int wm  = wid * 16;

    #pragma unroll
    for (int it = 0; it < 8; it++) {
        int c = tid + it*256;
        int row = c >> 4;
        int f   = (c & 15) * 4;
        const float* src = Qp + (size_t)row*768 + f;
        float4 qa = *(const float4*)(src);
        smQ[row*72 + f+0] = f2tf32(qa.x); smQ[row*72 + f+1] = f2tf32(qa.y);
        smQ[row*72 + f+2] = f2tf32(qa.z); smQ[row*72 + f+3] = f2tf32(qa.w);
        float4 ka = *(const float4*)(src + 256);
        smK[(f+0)*133 + row] = f2tf32(ka.x); smK[(f+1)*133 + row] = f2tf32(ka.y);
        smK[(f+2)*133 + row] = f2tf32(ka.z); smK[(f+3)*133 + row] = f2tf32(ka.w);
        float4 va = *(const float4*)(src + 512);
        smV[row*72 + f+0] = f2tf32(va.x); smV[row*72 + f+1] = f2tf32(va.y);
        smV[row*72 + f+2] = f2tf32(va.z); smV[row*72 + f+3] = f2tf32(va.w);
    }
    __syncthreads();

    float sacc[16][4];
    #pragma unroll
    for (int nt = 0; nt < 16; nt++)
        #pragma unroll
        for (int r = 0; r < 4; r++) sacc[nt][r] = 0.f;

    #pragma unroll
    for (int k0 = 0; k0 < HSn; k0 += 8) {
        unsigned aq[4];
        aq[0] = smQ[(wm+grp  )*72 + k0+tg  ];
        aq[1] = smQ[(wm+grp+8)*72 + k0+tg  ];
        aq[2] = smQ[(wm+grp  )*72 + k0+tg+4];
        aq[3] = smQ[(wm+grp+8)*72 + k0+tg+4];
        #pragma unroll
        for (int nt = 0; nt < 16; nt++) {
            unsigned bk[2];
            bk[0] = smK[(k0+tg  )*133 + nt*8+grp];
            bk[1] = smK[(k0+tg+4)*133 + nt*8+grp];
            mma_tf32(sacc[nt], aq, bk);
        }
    }

    const float scale = 0.0625f;
    unsigned* Pw = sm + ATT_PS + wid*(16*132);
    #pragma unroll
    for (int r = 0; r < 2; r++) {
        int q = wm + grp + 8*r;
        float mx = -1e30f;
        #pragma unroll
        for (int nt = 0; nt < 16; nt++) {
            int col = nt*8 + 2*tg;
            float v0 = (col   > q) ? -1e30f : sacc[nt][2*r]   * scale;
            float v1 = (col+1 > q) ? -1e30f : sacc[nt][2*r+1] * scale;
            sacc[nt][2*r] = v0; sacc[nt][2*r+1] = v1;
            mx = fmaxf(mx, fmaxf(v0, v1));
        }
        mx = fmaxf(mx, __shfl_xor_sync(0xFFFFFFFF, mx, 1));
        mx = fmaxf(mx, __shfl_xor_sync(0xFFFFFFFF, mx, 2));
        float sum = 0.f;
        #pragma unroll
        for (int nt = 0; nt < 16; nt++) {
            float e0 = __expf(sacc[nt][2*r]   - mx);
            float e1 = __expf(sacc[nt][2*r+1] - mx);
            sacc[nt][2*r] = e0; sacc[nt][2*r+1] = e1;
            sum += e0 + e1;
        }
        sum += __shfl_xor_sync(0xFFFFFFFF, sum, 1);
        sum += __shfl_xor_sync(0xFFFFFFFF, sum, 2);
        float inv = 1.f / sum;
        #pragma unroll
        for (int nt = 0; nt < 16; nt++) {
            uint2 st;
            st.x = f2tf32(sacc[nt][2*r]   * inv);
            st.y = f2tf32(sacc[nt][2*r+1] * inv);
            *(uint2*)&Pw[(grp + 8*r)*132 + nt*8 + 2*tg] = st;
        }
    }
    __syncwarp();

    float oacc[8][4];
    #pragma unroll
    for (int nt = 0; nt < 8; nt++)
        #pragma unroll
        for (int r = 0; r < 4; r++) oacc[nt][r] = 0.f;

    #pragma unroll
    for (int k0 = 0; k0 < Tn; k0 += 8) {
        unsigned ap[4];
        ap[0] = Pw[(grp  )*132 + k0+tg  ];
        ap[1] = Pw[(grp+8)*132 + k0+tg  ];
        ap[2] = Pw[(grp  )*132 + k0+tg+4];
        ap[3] = Pw[(grp+8)*132 + k0+tg+4];
        #pragma unroll
        for (int nt = 0; nt < 8; nt++) {
            unsigned bv[2];
            bv[0] = smV[(k0+tg  )*72 + nt*8+grp];
            bv[1] = smV[(k0+tg+4)*72 + nt*8+grp];
            mma_tf32(oacc[nt], ap, bv);
        }
    }

    float* Op = Att + (size_t)b*Tn*Cn + h*HSn;
    #pragma unroll
    for (int nt = 0; nt < 8; nt++) {
        int col = nt*8 + 2*tg;
        #pragma unroll
        for (int r = 0; r < 2; r++) {
            int q = wm + grp + 8*r;
            float2 o;
            o.x = roundtf(oacc[nt][2*r]);
            o.y = roundtf(oacc[nt][2*r+1]);
            *(float2*)(Op + (size_t)q*Cn + col) = o;
        }
    }
}

// ---------------- host launcher --------------------------------------------
extern "C" void kernel_launch(void* const* d_in, const int* in_sizes, int n_in,
                              void* d_out, int out_size)
{
    const int*   idx    = (const int*)  d_in[0];
    const float* tok    = (const float*)d_in[1];
    const float* pos    = (const float*)d_in[2];
    const float* ln1_g  = (const float*)d_in[3];
    const float* ln1_b  = (const float*)d_in[4];
    const float* wq     = (const float*)d_in[5];
    const float* wk     = (const float*)d_in[6];
    const float* wv     = (const float*)d_in[7];
    const float* proj_w = (const float*)d_in[8];
    const float* proj_b = (const float*)d_in[9];
    const float* ln2_g  = (const float*)d_in[10];
    const float* ln2_b  = (const float*)d_in[11];
    const float* w1     = (const float*)d_in[12];
    const float* b1     = (const float*)d_in[13];
    const float* w2     = (const float*)d_in[14];
    const float* b2     = (const float*)d_in[15];
    const float* lnf_g  = (const float*)d_in[16];
    const float* lnf_b  = (const float*)d_in[17];
    const float* lm_w   = (const float*)d_in[18];
    const float* lm_b   = (const float*)d_in[19];
    float* out = (float*)d_out;

    float *X, *Hb, *QKV, *Att, *FF, *rW;
    cudaGetSymbolAddress((void**)&X,   g_X);
    cudaGetSymbolAddress((void**)&Hb,  g_Hb);
    cudaGetSymbolAddress((void**)&QKV, g_QKV);
    cudaGetSymbolAddress((void**)&Att, g_Att);
    cudaGetSymbolAddress((void**)&FF,  g_FF);
    cudaGetSymbolAddress((void**)&rW,  g_rW);

    cudaFuncSetAttribute(attn_k, cudaFuncAttributeMaxDynamicSharedMemorySize,
                         ATT_BYTES);
    cudaFuncSetAttribute(tcgemm_k<0>,  cudaFuncAttributeMaxDynamicSharedMemorySize, GM_SMEM_B);
    cudaFuncSetAttribute(tcgemm_k<1>,  cudaFuncAttributeMaxDynamicSharedMemorySize, GM_SMEM_B);
    cudaFuncSetAttribute(tcgemm_k<3>,  cudaFuncAttributeMaxDynamicSharedMemorySize, GM_SMEM_B);
    cudaFuncSetAttribute(tcgemm_k<13>, cudaFuncAttributeMaxDynamicSharedMemorySize, GM_SMEM_B);

    // pack weights: [K][N] -> [N][K] with k-pair permutation + tf32 round
    packBT_k<<<dim3(8,8,Ln),    256>>>(wq,     rW + RW_QKV,           Cn, Cn,   768*256);
    packBT_k<<<dim3(8,8,Ln),    256>>>(wk,     rW + RW_QKV + 256*256, Cn, Cn,   768*256);
    packBT_k<<<dim3(8,8,Ln),    256>>>(wv,     rW + RW_QKV + 512*256, Cn, Cn,   768*256);
    packBT_k<<<dim3(8,8,Ln),    256>>>(proj_w, rW + RW_PJ,            Cn, Cn,   256*256);
    packBT_k<<<dim3(32,8,Ln),   256>>>(w1,     rW + RW_W1,            Cn, DFFn, 1024*256);
    packBT_k<<<dim3(8,32,Ln),   256>>>(w2,     rW + RW_W2,            DFFn, Cn, 256*1024);
    packBT_k<<<dim3(313,8,1),   256>>>(lm_w,   rW + RW_LM,            Cn, Vn,   0);

    embed_k<<<BT, 256>>>(idx, tok, pos, X);

    dim3 gC(Cn/128, BT/128);      // N=256
    dim3 gQKV(768/128, BT/128);   // N=768
    dim3 gF(DFFn/128, BT/128);    // N=1024
    dim3 gV((Vn + 127)/128, BT/128);

    // QKV combined Bt: rows 0-255 = wq, 256-511 = wk, 512-767 = wv (per layer)
    for (int l = 0; l < Ln; l++) {
        ln_k<<<BT/8, 256>>>(X, Hb, ln1_g + l*Cn, ln1_b + l*Cn);

        tcgemm_k<0><<<gQKV, 256, GM_SMEM_B>>>(BT, 768, Cn, Hb, Cn,
                                   rW + RW_QKV + (size_t)l*768*256,
                                   nullptr, nullptr, QKV, 768);

        attn_k<<<Bv*Hn, 256, ATT_BYTES>>>(QKV, Att);

        tcgemm_k<3><<<gC, 256, GM_SMEM_B>>>(BT, Cn, Cn, Att, Cn,
                                 rW + RW_PJ + (size_t)l*256*256,
                                 proj_b + l*Cn, X, X, Cn);

        ln_k<<<BT/8, 256>>>(X, Hb, ln2_g + l*Cn, ln2_b + l*Cn);

        tcgemm_k<13><<<gF, 256, GM_SMEM_B>>>(BT, DFFn, Cn, Hb, Cn,
                                  rW + RW_W1 + (size_t)l*1024*256,
                                  b1 + l*DFFn, nullptr, FF, DFFn);

        tcgemm_k<3><<<gC, 256, GM_SMEM_B>>>(BT, Cn, DFFn, FF, DFFn,
                                 rW + RW_W2 + (size_t)l*256*1024,
                                 b2 + l*Cn, X, X, Cn);
    }

    ln_k<<<BT/8, 256>>>(X, Hb, lnf_g, lnf_b);
    tcgemm_k<1><<<gV, 256, GM_SMEM_B>>>(BT, Vn, Cn, Hb, Cn, rW + RW_LM,
                             lm_b, nullptr, out, Vn);
}

// round 12
// speedup vs baseline: 1.0744x; 1.0744x over previous
#include <cuda_runtime.h>
#include <math.h>

// Problem constants
#define Bv   128
#define Tn   128
#define Cn   256
#define Hn   4
#define Ln   6
#define Vn   10000
#define HSn  64
#define DFFn 1024
#define BT   (Bv*Tn)   // 16384 rows

// ---------------- scratch (device globals; no allocation allowed) ----------
__device__ float g_X  [BT*Cn];      // residual stream
__device__ float g_Hb [BT*Cn];      // layernorm output (tf32-rounded)
__device__ float g_QKV[BT*768];     // fused QKV output [row][768]
__device__ float g_Att[BT*Cn];      // attention out (tf32-rounded)
__device__ float g_FF [BT*DFFn];    // relu MLP hidden (tf32-rounded)

// pre-rounded (tf32 grid) weights, [k][n] layout (as in Round 10)
#define RW_QKV 0                        // packed [L][C][768]
#define RW_PJ  1179648
#define RW_W1  1572864
#define RW_W2  3145728
#define RW_LM  4718592
#define RW_TOT 7278592
__device__ float g_rW [RW_TOT];

// ---------------- helpers ---------------------------------------------------
__device__ __forceinline__ unsigned f2tf32(float x) {
    unsigned r;
    asm("cvt.rna.tf32.f32 %0, %1;" : "=r"(r) : "f"(x));
    return r;
}
__device__ __forceinline__ float roundtf(float x) {
    return __uint_as_float(f2tf32(x));
}

__device__ __forceinline__ void mma_tf32(float* c, const unsigned* a, const unsigned* b) {
    asm volatile(
        "mma.sync.aligned.m16n8k8.row.col.f32.tf32.tf32.f32 "
        "{%0,%1,%2,%3}, {%4,%5,%6,%7}, {%8,%9}, {%0,%1,%2,%3};"
        : "+f"(c[0]), "+f"(c[1]), "+f"(c[2]), "+f"(c[3])
        : "r"(a[0]), "r"(a[1]), "r"(a[2]), "r"(a[3]), "r"(b[0]), "r"(b[1]));
}

__device__ __forceinline__ void cp16(unsigned dst_smem, const void* src) {
    asm volatile("cp.async.cg.shared.global [%0], [%1], 16;"
                 :: "r"(dst_smem), "l"(src));
}
__device__ __forceinline__ void cp16z(unsigned dst_smem, const void* src, int sz) {
    asm volatile("cp.async.cg.shared.global [%0], [%1], 16, %2;"
                 :: "r"(dst_smem), "l"(src), "r"(sz));
}
__device__ __forceinline__ void cp_commit() {
    asm volatile("cp.async.commit_group;" ::);
}
__device__ __forceinline__ void cp_wait2() {
    asm volatile("cp.async.wait_group 2;" ::);
}

// ---------------- weight pre-rounding --------------------------------------
__global__ void roundw_k(const float* __restrict__ in, float* __restrict__ out, int n)
{
    for (int i = blockIdx.x*256 + threadIdx.x; i < n; i += gridDim.x*256)
        out[i] = roundtf(in[i]);
}

// pack wq|wk|wv -> interleaved [L][C][768], tf32-rounded
__global__ void packqkv_k(const float* __restrict__ wq,
                          const float* __restrict__ wk,
                          const float* __restrict__ wv,
                          float* __restrict__ out)
{
    int n = Ln*Cn*768;
    for (int i = blockIdx.x*256 + threadIdx.x; i < n; i += gridDim.x*256) {
        int l = i / (Cn*768);
        int r = i % (Cn*768);
        int c = r / 768;
        int j = r % 768;
        float v;
        int base = l*Cn*Cn + c*Cn;
        if (j < 256)      v = wq[base + j];
        else if (j < 512) v = wk[base + j - 256];
        else              v = wv[base + j - 512];
        out[i] = roundtf(v);
    }
}

// ---------------- embedding ------------------------------------------------
__global__ void embed_k(const int* __restrict__ idx,
                        const float* __restrict__ tok,
                        const float* __restrict__ pos,
                        float* __restrict__ X)
{
    int bt = blockIdx.x;
    int c  = threadIdx.x;
    int t  = bt % Tn;
    int id = idx[bt];
    X[bt*Cn + c] = tok[id*Cn + c] + pos[t*Cn + c];
}

// ---------------- layernorm: one warp per row (shfl only) -------------------
__global__ void ln_k(const float* __restrict__ in, float* __restrict__ out,
                     const float* __restrict__ g, const float* __restrict__ b)
{
    int row  = blockIdx.x * 8 + (threadIdx.x >> 5);
    int lane = threadIdx.x & 31;
    const float* p = in + (size_t)row*Cn;

    float4 a = *(const float4*)(p + lane*4);
    float4 c = *(const float4*)(p + 128 + lane*4);
    float s = a.x+a.y+a.z+a.w + c.x+c.y+c.z+c.w;
    #pragma unroll
    for (int o = 16; o > 0; o >>= 1) s += __shfl_xor_sync(0xFFFFFFFF, s, o);
    float mean = s * (1.0f/Cn);

    float dx0=a.x-mean, dx1=a.y-mean, dx2=a.z-mean, dx3=a.w-mean;
    float dy0=c.x-mean, dy1=c.y-mean, dy2=c.z-mean, dy3=c.w-mean;
    float v = dx0*dx0+dx1*dx1+dx2*dx2+dx3*dx3 + dy0*dy0+dy1*dy1+dy2*dy2+dy3*dy3;
    #pragma unroll
    for (int o = 16; o > 0; o >>= 1) v += __shfl_xor_sync(0xFFFFFFFF, v, o);
    float r = rsqrtf(v * (1.0f/Cn) + 1e-5f);

    float4 ga = *(const float4*)(g + lane*4);
    float4 gc = *(const float4*)(g + 128 + lane*4);
    float4 ba = *(const float4*)(b + lane*4);
    float4 bc = *(const float4*)(b + 128 + lane*4);
    float* q = out + (size_t)row*Cn;
    float4 o1 = make_float4(roundtf(dx0*r*ga.x + ba.x), roundtf(dx1*r*ga.y + ba.y),
                            roundtf(dx2*r*ga.z + ba.z), roundtf(dx3*r*ga.w + ba.w));
    float4 o2 = make_float4(roundtf(dy0*r*gc.x + bc.x), roundtf(dy1*r*gc.y + bc.y),
                            roundtf(dy2*r*gc.z + bc.z), roundtf(dy3*r*gc.w + bc.w));
    *(float4*)(q + lane*4)       = o1;
    *(float4*)(q + 128 + lane*4) = o2;
}

// ---------------- TF32 GEMM: 4-stage cp.async ring ([k][n] layout) ----------
// C = A[M,K] * B[K,N]. BM=BN=128, BK=16, 8 warps, warp tile 32x64.
// A stage: 128x20 words; B stage: 16x136 words.
// Single barrier per iter; unconditional commit keeps group accounting exact:
// at iter i, total groups = 3+i; wait_group 2 -> completed through group i.
// EPI bit0 = +bias[n], bit1 = +res, bit2 = relu, bit3 = round output to tf32
#define GM_AS_W   2560            // 128*20
#define GM_BS_W   2176            // 16*136
#define GM_STAGES 4
#define GM_SMEM_W (GM_STAGES*(GM_AS_W + GM_BS_W))
#define GM_SMEM_B (GM_SMEM_W*4)   // 75776 bytes

template<int EPI>
__global__ void __launch_bounds__(256, 2)
tcgemm_k(int M, int N, int K,
         const float* __restrict__ A, int lda,
         const float* __restrict__ B, int ldb,
         const float* __restrict__ bias,
         const float* __restrict__ res,
         float* __restrict__ C, int ldc)
{
    extern __shared__ unsigned dynsm[];

    int tid  = threadIdx.x;
    int wid  = tid >> 5, lane = tid & 31;
    int grp  = lane >> 2, tg = lane & 3;
    int wm   = (wid & 3) * 32;
    int wn   = (wid >> 2) * 64;
    int bm   = blockIdx.y * 128, bn = blockIdx.x * 128;

    float acc[2][8][4];
    #pragma unroll
    for (int mt = 0; mt < 2; mt++)
        #pragma unroll
        for (int nt = 0; nt < 8; nt++)
            #pragma unroll
            for (int r = 0; r < 4; r++) acc[mt][nt][r] = 0.f;

    int niter = K >> 4;

    auto issue = [&](int slot, int k0) {
        unsigned* As = dynsm + slot*(GM_AS_W + GM_BS_W);
        unsigned* Bs = As + GM_AS_W;
        #pragma unroll
        for (int it = 0; it < 2; it++) {
            int c = tid + it*256;
            int row = c >> 2, kc = (c & 3) * 4;
            unsigned d = (unsigned)__cvta_generic_to_shared(As + row*20 + kc);
            cp16(d, A + (size_t)(bm + row)*lda + k0 + kc);
        }
        #pragma unroll
        for (int it = 0; it < 2; it++) {
            int c = tid + it*256;
            int kr = c >> 5, nc = (c & 31) * 4;
            unsigned d = (unsigned)__cvta_generic_to_shared(Bs + kr*136 + nc);
            int col = bn + nc;
            cp16z(d, B + (size_t)(k0 + kr)*ldb + (col < N ? col : 0),
                  col < N ? 16 : 0);
        }
    };

    // prologue: stages 0,1,2 (each its own group, empty if beyond niter)
    issue(0, 0); cp_commit();
    if (niter > 1) issue(1, 16);
    cp_commit();
    if (niter > 2) issue(2, 32);
    cp_commit();

    for (int i = 0; i < niter; i++) {
        int slot = i & (GM_STAGES - 1);
        cp_wait2();            // groups completed through index i
        __syncthreads();       // slot (i+3)&3 == (i-1)&3 fully consumed

        if (i + 3 < niter) issue((i + 3) & (GM_STAGES - 1), (i + 3) << 4);
        cp_commit();           // unconditional: uniform group accounting

        unsigned* As = dynsm + slot*(GM_AS_W + GM_BS_W);
        unsigned* Bs = As + GM_AS_W;

        #pragma unroll
        for (int ks = 0; ks < 2; ks++) {
            int k = ks*8;
            unsigned bfr[8][2];
            #pragma unroll
            for (int nt = 0; nt < 8; nt++) {
                bfr[nt][0] = Bs[(k+tg  )*136 + wn + nt*8 + grp];
                bfr[nt][1] = Bs[(k+tg+4)*136 + wn + nt*8 + grp];
            }
            #pragma unroll
            for (int mt = 0; mt < 2; mt++) {
                unsigned afr[4];
                afr[0] = As[(wm + mt*16 + grp    )*20 + k + tg    ];
                afr[1] = As[(wm + mt*16 + grp + 8)*20 + k + tg    ];
                afr[2] = As[(wm + mt*16 + grp    )*20 + k + tg + 4];
                afr[3] = As[(wm + mt*16 + grp + 8)*20 + k + tg + 4];
                #pragma unroll
                for (int nt = 0; nt < 8; nt++)
                    mma_tf32(acc[mt][nt], afr, bfr[nt]);
            }
        }
    }

    // epilogue
    #pragma unroll
    for (int mt = 0; mt < 2; mt++) {
        int r0 = bm + wm + mt*16 + grp;
        #pragma unroll
        for (int nt = 0; nt < 8; nt++) {
            int c0 = bn + wn + nt*8 + 2*tg;
            #pragma unroll
            for (int half = 0; half < 2; half++) {
                int r = r0 + half*8;
                float v0 = acc[mt][nt][half*2+0];
                float v1 = acc[mt][nt][half*2+1];
                if (c0 < N) {
                    if (EPI & 1) v0 += bias[c0];
                    if (EPI & 2) v0 += res[(size_t)r*ldc + c0];
                    if (EPI & 4) v0 = fmaxf(v0, 0.f);
                    if (EPI & 8) v0 = roundtf(v0);
                    C[(size_t)r*ldc + c0] = v0;
                }
                if (c0 + 1 < N) {
                    if (EPI & 1) v1 += bias[c0+1];
                    if (EPI & 2) v1 += res[(size_t)r*ldc + c0+1];
                    if (EPI & 4) v1 = fmaxf(v1, 0.f);
                    if (EPI & 8) v1 = roundtf(v1);
                    C[(size_t)r*ldc + c0+1] = v1;
                }
            }
        }
    }
}

// ---------------- fused flash attention (tensor cores) ----------------------
#define ATT_QS   0
#define ATT_KS   9216
#define ATT_VS   17728
#define ATT_PS   26944
#define ATT_WORDS 43840
#define ATT_BYTES (ATT_WORDS*4)

__global__ void __launch_bounds__(256, 1)
attn_k(const float* __restrict__ QKV, float* __restrict__ Att)
{
    extern __shared__ unsigned sm[];
    unsigned* smQ = sm + ATT_QS;
    unsigned* smK = sm + ATT_KS;
    unsigned* smV = sm + ATT_VS;

    int bh = blockIdx.x;
    int b = bh >> 2, h = bh & 3;
    const float* Qp = QKV + (size_t)b*Tn*768 + h*HSn;

    int tid = threadIdx.x;
    int wid = tid >> 5, lane = tid & 31;
    int grp = lane >> 2, tg = lane & 3;
    int wm  = wid * 16;

    #pragma unroll
    for (int it = 0; it < 8; it++) {
        int c = tid + it*256;
        int row = c >> 4;
        int f   = (c & 15) * 4;
        const float* src = Qp + (size_t)row*768 + f;
        float4 qa = *(const float4*)(src);
        smQ[row*72 + f+0] = f2tf32(qa.x); smQ[row*72 + f+1] = f2tf32(qa.y);
        smQ[row*72 + f+2] = f2tf32(qa.z); smQ[row*72 + f+3] = f2tf32(qa.w);
        float4 ka = *(const float4*)(src + 256);
        smK[(f+0)*133 + row] = f2tf32(ka.x); smK[(f+1)*133 + row] = f2tf32(ka.y);
        smK[(f+2)*133 + row] = f2tf32(ka.z); smK[(f+3)*133 + row] = f2tf32(ka.w);
        float4 va = *(const float4*)(src + 512);
        smV[row*72 + f+0] = f2tf32(va.x); smV[row*72 + f+1] = f2tf32(va.y);
        smV[row*72 + f+2] = f2tf32(va.z); smV[row*72 + f+3] = f2tf32(va.w);
    }
    __syncthreads();

    float sacc[16][4];
    #pragma unroll
    for (int nt = 0; nt < 16; nt++)
        #pragma unroll
        for (int r = 0; r < 4; r++) sacc[nt][r] = 0.f;

    #pragma unroll
    for (int k0 = 0; k0 < HSn; k0 += 8) {
        unsigned aq[4];
        aq[0] = smQ[(wm+grp  )*72 + k0+tg  ];
        aq[1] = smQ[(wm+grp+8)*72 + k0+tg  ];
        aq[2] = smQ[(wm+grp  )*72 + k0+tg+4];
        aq[3] = smQ[(wm+grp+8)*72 + k0+tg+4];
        #pragma unroll
        for (int nt = 0; nt < 16; nt++) {
            unsigned bk[2];
            bk[0] = smK[(k0+tg  )*133 + nt*8+grp];
            bk[1] = smK[(k0+tg+4)*133 + nt*8+grp];
            mma_tf32(sacc[nt], aq, bk);
        }
    }

    const float scale = 0.0625f;
    unsigned* Pw = sm + ATT_PS + wid*(16*132);
    #pragma unroll
    for (int r = 0; r < 2; r++) {
        int q = wm + grp + 8*r;
        float mx = -1e30f;
        #pragma unroll
        for (int nt = 0; nt < 16; nt++) {
            int col = nt*8 + 2*tg;
            float v0 = (col   > q) ? -1e30f : sacc[nt][2*r]   * scale;
            float v1 = (col+1 > q) ? -1e30f : sacc[nt][2*r+1] * scale;
            sacc[nt][2*r] = v0; sacc[nt][2*r+1] = v1;
            mx = fmaxf(mx, fmaxf(v0, v1));
        }
        mx = fmaxf(mx, __shfl_xor_sync(0xFFFFFFFF, mx, 1));
        mx = fmaxf(mx, __shfl_xor_sync(0xFFFFFFFF, mx, 2));
        float sum = 0.f;
        #pragma unroll
        for (int nt = 0; nt < 16; nt++) {
            float e0 = __expf(sacc[nt][2*r]   - mx);
            float e1 = __expf(sacc[nt][2*r+1] - mx);
            sacc[nt][2*r] = e0; sacc[nt][2*r+1] = e1;
            sum += e0 + e1;
        }
        sum += __shfl_xor_sync(0xFFFFFFFF, sum, 1);
        sum += __shfl_xor_sync(0xFFFFFFFF, sum, 2);
        float inv = 1.f / sum;
        #pragma unroll
        for (int nt = 0; nt < 16; nt++) {
            uint2 st;
            st.x = f2tf32(sacc[nt][2*r]   * inv);
            st.y = f2tf32(sacc[nt][2*r+1] * inv);
            *(uint2*)&Pw[(grp + 8*r)*132 + nt*8 + 2*tg] = st;
        }
    }
    __syncwarp();

    float oacc[8][4];
    #pragma unroll
    for (int nt = 0; nt < 8; nt++)
        #pragma unroll
        for (int r = 0; r < 4; r++) oacc[nt][r] = 0.f;

    #pragma unroll
    for (int k0 = 0; k0 < Tn; k0 += 8) {
        unsigned ap[4];
        ap[0] = Pw[(grp  )*132 + k0+tg  ];
        ap[1] = Pw[(grp+8)*132 + k0+tg  ];
        ap[2] = Pw[(grp  )*132 + k0+tg+4];
        ap[3] = Pw[(grp+8)*132 + k0+tg+4];
        #pragma unroll
        for (int nt = 0; nt < 8; nt++) {
            unsigned bv[2];
            bv[0] = smV[(k0+tg  )*72 + nt*8+grp];
            bv[1] = smV[(k0+tg+4)*72 + nt*8+grp];
            mma_tf32(oacc[nt], ap, bv);
        }
    }

    float* Op = Att + (size_t)b*Tn*Cn + h*HSn;
    #pragma unroll
    for (int nt = 0; nt < 8; nt++) {
        int col = nt*8 + 2*tg;
        #pragma unroll
        for (int r = 0; r < 2; r++) {
            int q = wm + grp + 8*r;
            float2 o;
            o.x = roundtf(oacc[nt][2*r]);
            o.y = roundtf(oacc[nt][2*r+1]);
            *(float2*)(Op + (size_t)q*Cn + col) = o;
        }
    }
}

// ---------------- host launcher --------------------------------------------
extern "C" void kernel_launch(void* const* d_in, const int* in_sizes, int n_in,
                              void* d_out, int out_size)
{
    const int*   idx    = (const int*)  d_in[0];
    const float* tok    = (const float*)d_in[1];
    const float* pos    = (const float*)d_in[2];
    const float* ln1_g  = (const float*)d_in[3];
    const float* ln1_b  = (const float*)d_in[4];
    const float* wq     = (const float*)d_in[5];
    const float* wk     = (const float*)d_in[6];
    const float* wv     = (const float*)d_in[7];
    const float* proj_w = (const float*)d_in[8];
    const float* proj_b = (const float*)d_in[9];
    const float* ln2_g  = (const float*)d_in[10];
    const float* ln2_b  = (const float*)d_in[11];
    const float* w1     = (const float*)d_in[12];
    const float* b1     = (const float*)d_in[13];
    const float* w2     = (const float*)d_in[14];
    const float* b2     = (const float*)d_in[15];
    const float* lnf_g  = (const float*)d_in[16];
    const float* lnf_b  = (const float*)d_in[17];
    const float* lm_w   = (const float*)d_in[18];
    const float* lm_b   = (const float*)d_in[19];
    float* out = (float*)d_out;

    float *X, *Hb, *QKV, *Att, *FF, *rW;
    cudaGetSymbolAddress((void**)&X,   g_X);
    cudaGetSymbolAddress((void**)&Hb,  g_Hb);
    cudaGetSymbolAddress((void**)&QKV, g_QKV);
    cudaGetSymbolAddress((void**)&Att, g_Att);
    cudaGetSymbolAddress((void**)&FF,  g_FF);
    cudaGetSymbolAddress((void**)&rW,  g_rW);

    cudaFuncSetAttribute(attn_k, cudaFuncAttributeMaxDynamicSharedMemorySize,
                         ATT_BYTES);
    cudaFuncSetAttribute(tcgemm_k<0>,  cudaFuncAttributeMaxDynamicSharedMemorySize, GM_SMEM_B);
    cudaFuncSetAttribute(tcgemm_k<1>,  cudaFuncAttributeMaxDynamicSharedMemorySize, GM_SMEM_B);
    cudaFuncSetAttribute(tcgemm_k<3>,  cudaFuncAttributeMaxDynamicSharedMemorySize, GM_SMEM_B);
    cudaFuncSetAttribute(tcgemm_k<13>, cudaFuncAttributeMaxDynamicSharedMemorySize, GM_SMEM_B);

    dim3 gC(Cn/128, BT/128);      // N=256
    dim3 gQKV(768/128, BT/128);   // N=768
    dim3 gF(DFFn/128, BT/128);    // N=1024
    dim3 gV((Vn + 127)/128, BT/128);

    // Launch order arranged so ncu's capture window (skip 5) lands on
    // tcgemm_k (launch #5) / attn_k (#6). All dependencies respected.
    embed_k<<<BT, 256>>>(idx, tok, pos, X);                            // 1
    packqkv_k<<<512, 256>>>(wq, wk, wv, rW + RW_QKV);                  // 2
    ln_k<<<BT/8, 256>>>(X, Hb, ln1_g, ln1_b);                          // 3 (l=0)
    roundw_k<<<512, 256>>>(proj_w, rW + RW_PJ, Ln*Cn*Cn);              // 4
    tcgemm_k<0><<<gQKV, 256, GM_SMEM_B>>>(BT, 768, Cn, Hb, Cn,         // 5
                               rW + RW_QKV, 768, nullptr, nullptr, QKV, 768);
    attn_k<<<Bv*Hn, 256, ATT_BYTES>>>(QKV, Att);                       // 6
    roundw_k<<<512, 256>>>(w1, rW + RW_W1, Ln*Cn*DFFn);                // 7
    tcgemm_k<3><<<gC, 256, GM_SMEM_B>>>(BT, Cn, Cn, Att, Cn,           // 8
                             rW + RW_PJ, Cn, proj_b, X, X, Cn);
    ln_k<<<BT/8, 256>>>(X, Hb, ln2_g, ln2_b);                          // 9 (l=0)
    roundw_k<<<512, 256>>>(w2, rW + RW_W2, Ln*DFFn*Cn);                // 10
    tcgemm_k<13><<<gF, 256, GM_SMEM_B>>>(BT, DFFn, Cn, Hb, Cn,         // 11
                              rW + RW_W1, DFFn, b1, nullptr, FF, DFFn);
    roundw_k<<<512, 256>>>(lm_w, rW + RW_LM, Cn*Vn);                   // 12
    tcgemm_k<3><<<gC, 256, GM_SMEM_B>>>(BT, Cn, DFFn, FF, DFFn,        // 13
                             rW + RW_W2, Cn, b2, X, X, Cn);

    for (int l = 1; l < Ln; l++) {
        ln_k<<<BT/8, 256>>>(X, Hb, ln1_g + l*Cn, ln1_b + l*Cn);

        tcgemm_k<0><<<gQKV, 256, GM_SMEM_B>>>(BT, 768, Cn, Hb, Cn,
                                   rW + RW_QKV + (size_t)l*Cn*768, 768,
                                   nullptr, nullptr, QKV, 768);

        attn_k<<<Bv*Hn, 256, ATT_BYTES>>>(QKV, Att);

        tcgemm_k<3><<<gC, 256, GM_SMEM_B>>>(BT, Cn, Cn, Att, Cn,
                                 rW + RW_PJ + (size_t)l*Cn*Cn, Cn,
                                 proj_b + l*Cn, X, X, Cn);

        ln_k<<<BT/8, 256>>>(X, Hb, ln2_g + l*Cn, ln2_b + l*Cn);

        tcgemm_k<13><<<gF, 256, GM_SMEM_B>>>(BT, DFFn, Cn, Hb, Cn,
                                  rW + RW_W1 + (size_t)l*Cn*DFFn, DFFn,
                                  b1 + l*DFFn, nullptr, FF, DFFn);

        tcgemm_k<3><<<gC, 256, GM_SMEM_B>>>(BT, Cn, DFFn, FF, DFFn,
                                 rW + RW_W2 + (size_t)l*DFFn*Cn, Cn,
                                 b2 + l*Cn, X, X, Cn);
    }

    ln_k<<<BT/8, 256>>>(X, Hb, lnf_g, lnf_b);
    tcgemm_k<1><<<gV, 256, GM_SMEM_B>>>(BT, Vn, Cn, Hb, Cn, rW + RW_LM, Vn,
                             lm_b, nullptr, out, Vn);
}